// round 12
// baseline (speedup 1.0000x reference)
#include <cuda_runtime.h>
#include <cstdint>

// Problem constants (fixed shapes)
#define PN    100000   // nodes
#define PE    100000   // hyperedges
#define PNNZ  800000   // edges (nnz)
#define PR    4        // ranks
#define PF    64       // features

#define NTILE 1024
#define NB_C  ((PE + NTILE - 1) / NTILE)   // 98
#define NB_R  ((PN + NTILE - 1) / NTILE)   // 98

// ---- scratch (__device__ globals; no allocation). ~42 MB total.
// RULE (hard-won in rounds 3-6): these symbols are referenced ONLY from
// device code; never passed as host-side kernel arguments (host shadow
// address = UB = 128 MB checkpoint violation).
__device__ int    g_is64;
__device__ int    g_alloc_c;             // tile-region allocator (col bins)
__device__ int    g_alloc_r;             // tile-region allocator (row bins)
__device__ int    g_cnt_c[PE];           // zeroed by gather_edge_feat for next replay
__device__ int    g_cnt_r[PN];           // zeroed by gather_node_feat for next replay
__device__ int    g_ptr_c[PE];
__device__ int    g_ptr_r[PN];
__device__ int    g_cur_c[PE];
__device__ int    g_cur_r[PN];
__device__ __align__(16) float4 g_scales[PE];                 // (rm0,rm1,rm2,_)[he_idxs[c]]  1.6 MB
__device__ __align__(16) float  g_he_feat[(size_t)PE * PF];   // 25.6 MB dense
__device__ __align__(8)  int2   g_e1[PNNZ];   // by col-bin: (row, val bits)   6.4 MB
__device__ __align__(8)  int2   g_e2[PNNZ];   // by row-bin: (col, val bits)   6.4 MB

__device__ __forceinline__ long long load_idx(const void* p, long long i, int is64) {
    if (is64) return ((const long long*)p)[i];
    return (long long)((const int*)p)[i];
}

// --- dtype sniff (warp-parallel) + allocator reset (every replay).
// int64 LE indices < 2^31 -> every odd 32-bit word is 0. 1024 words checked.
__global__ void detect_and_reset(const void* rows) {
    const int* p = (const int*)rows;
    int lane = threadIdx.x;
    int found = 0;
    #pragma unroll
    for (int k = 0; k < 32; k++) {
        int i = lane + 32 * k;            // word index among odd words
        if (p[2 * i + 1] != 0) found = 1;
    }
    unsigned any = __ballot_sync(0xFFFFFFFFu, found);
    if (lane == 0) {
        g_is64 = (any == 0u);
        g_alloc_c = 0;
        g_alloc_r = 0;
    }
}

// --- histogram edges by col and by row; fused per-hyperedge scale precompute
//     (threads e < PE also build g_scales[e] = rank_masks[0..2, he_idxs[e]])
//     Counters arrive zeroed: BSS init on first run, gather-kernel tails after.
__global__ void histogram_edges(const void* __restrict__ rows,
                                const void* __restrict__ cols,
                                const void* __restrict__ he_idxs,
                                const float* __restrict__ rank_masks) {
    int is64 = g_is64;
    long long e = (long long)blockIdx.x * blockDim.x + threadIdx.x;
    if (e >= PNNZ) return;
    int row = (int)load_idx(rows, e, is64);
    int col = (int)load_idx(cols, e, is64);
    atomicAdd(&g_cnt_c[col], 1);
    atomicAdd(&g_cnt_r[row], 1);
    if (e < PE) {
        long long he = load_idx(he_idxs, e, is64);
        g_scales[e] = make_float4(rank_masks[he],
                                  rank_masks[(size_t)PE + he],
                                  rank_masks[(size_t)2 * PE + he],
                                  0.0f);
    }
}

// --- single-kernel offset assignment: per-tile smem scan + atomic region grab.
// Bins need only DISJOINT contiguous regions, not index-ordered ones, so each
// tile claims its span with one atomicAdd. Gathers use ptr[] + cnt[] for ends.
__global__ void assign_offsets() {
    __shared__ int sm[NTILE];
    __shared__ int base_sh;
    int b = blockIdx.x;
    bool isC = (b < NB_C);
    const int* cnt = isC ? g_cnt_c : g_cnt_r;
    int*       ptr = isC ? g_ptr_c : g_ptr_r;
    int*       cur = isC ? g_cur_c : g_cur_r;
    int n    = isC ? PE : PN;
    int tile = isC ? b : b - NB_C;
    int t = threadIdx.x;
    int i = tile * NTILE + t;
    int v = (i < n) ? cnt[i] : 0;
    sm[t] = v;
    __syncthreads();
    #pragma unroll
    for (int d = 1; d < NTILE; d <<= 1) {
        int u = (t >= d) ? sm[t - d] : 0;
        __syncthreads();
        sm[t] += u;
        __syncthreads();
    }
    if (t == NTILE - 1)
        base_sh = atomicAdd(isC ? &g_alloc_c : &g_alloc_r, sm[t]);
    __syncthreads();
    if (i < n) {
        int p = base_sh + sm[t] - v;   // exclusive within tile + tile base
        ptr[i] = p;
        cur[i] = p;
    }
}

// --- scatter edges into both bin layouts (one edge per thread — cross-warp
//     MLP beats intra-thread batching for scattered atomics; R10 evidence).
__global__ void scatter_fill(const float* __restrict__ vals,
                             const void* __restrict__ rows,
                             const void* __restrict__ cols) {
    int is64 = g_is64;
    long long e = (long long)blockIdx.x * blockDim.x + threadIdx.x;
    if (e >= PNNZ) return;
    int row = (int)load_idx(rows, e, is64);
    int col = (int)load_idx(cols, e, is64);
    int vbits = __float_as_int(vals[e]);

    int p1 = atomicAdd(&g_cur_c[col], 1);
    g_e1[p1] = make_int2(row, vbits);

    int p2 = atomicAdd(&g_cur_r[row], 1);
    g_e2[p2] = make_int2(col, vbits);
}

// --- pass 1 (gather): he_feat[c, :] = sum over edges in col-bin c of x[row]*val
//     16 threads per hyperedge; each owns one float4 of the 64-float row.
//     Tail: zero g_cnt_c[g] for the next replay's histogram.
__global__ void gather_edge_feat(const float4* __restrict__ x4) {
    long long g = ((long long)blockIdx.x * blockDim.x + threadIdx.x) >> 4;
    int sub = threadIdx.x & 15;
    if (g >= PE) return;
    int beg = g_ptr_c[g];
    int end = beg + g_cnt_c[g];
    float4 acc = make_float4(0.f, 0.f, 0.f, 0.f);
    #pragma unroll 2
    for (int i = beg; i < end; i++) {
        int2 eRec = g_e1[i];
        float v = __int_as_float(eRec.y);
        float4 a = x4[(long long)eRec.x * 16 + sub];
        acc.x += a.x * v; acc.y += a.y * v; acc.z += a.z * v; acc.w += a.w * v;
    }
    ((float4*)g_he_feat)[g * 16 + sub] = acc;   // dense, coalesced
    if (sub == 0) g_cnt_c[g] = 0;               // self-clean for next replay
}

// --- pass 2 (gather, fused with rank-3 init):
//     out[n, r, :] = sum over edges in row-bin n of
//         (g_scales[col].r * val) * he_feat[col, :]   (r = 0..2)
//     out[n, 3, :] = x[n, :]   -- full 1 KB node row written contiguously.
//     Tail: zero g_cnt_r[n] for the next replay's histogram.
__global__ void gather_node_feat(float4* __restrict__ out4,
                                 const float4* __restrict__ x4) {
    long long n = ((long long)blockIdx.x * blockDim.x + threadIdx.x) >> 4;
    int sub = threadIdx.x & 15;
    if (n >= PN) return;
    int beg = g_ptr_r[n];
    int end = beg + g_cnt_r[n];
    const float4* hf4 = (const float4*)g_he_feat;
    float4 a0 = make_float4(0.f, 0.f, 0.f, 0.f);
    float4 a1 = a0, a2 = a0;
    #pragma unroll 2
    for (int i = beg; i < end; i++) {
        int2 m = g_e2[i];
        int col = m.x;
        float v = __int_as_float(m.y);
        float4 sc = g_scales[col];          // broadcast across the 16 lanes; L2-hot
        float4 h  = hf4[(long long)col * 16 + sub];
        float s0 = sc.x * v, s1 = sc.y * v, s2 = sc.z * v;
        a0.x += h.x * s0; a0.y += h.y * s0; a0.z += h.z * s0; a0.w += h.w * s0;
        a1.x += h.x * s1; a1.y += h.y * s1; a1.z += h.z * s1; a1.w += h.w * s1;
        a2.x += h.x * s2; a2.y += h.y * s2; a2.z += h.z * s2; a2.w += h.w * s2;
    }
    float4* o = out4 + n * 64;          // 64 float4 per node row (R*F = 256 floats)
    o[sub]      = a0;
    o[16 + sub] = a1;
    o[32 + sub] = a2;
    o[48 + sub] = x4[n * 16 + sub];     // fused rank-3 = x
    if (sub == 0) g_cnt_r[n] = 0;       // self-clean for next replay
}

extern "C" void kernel_launch(void* const* d_in, const int* in_sizes, int n_in,
                              void* d_out, int out_size) {
    const float* x          = (const float*)d_in[0];   // (N, F)
    const float* rank_masks = (const float*)d_in[1];   // (R, E)
    const float* vals       = (const float*)d_in[2];   // (NNZ,)
    const void*  he_idxs    = d_in[3];                 // (E,)
    const void*  rows       = d_in[4];                 // (NNZ,)
    const void*  cols       = d_in[5];                 // (NNZ,)
    float4* out4 = (float4*)d_out;                     // (N, R, F)

    detect_and_reset<<<1, 32>>>(rows);

    histogram_edges<<<(PNNZ + 255) / 256, 256>>>(rows, cols, he_idxs, rank_masks);

    assign_offsets<<<NB_C + NB_R, NTILE>>>();

    scatter_fill<<<(PNNZ + 255) / 256, 256>>>(vals, rows, cols);

    {
        long long threads = (long long)PE * 16;
        gather_edge_feat<<<(int)((threads + 255) / 256), 256>>>((const float4*)x);
    }
    {
        long long threads = (long long)PN * 16;
        gather_node_feat<<<(int)((threads + 255) / 256), 256>>>(out4, (const float4*)x);
    }
}

// round 13
// speedup vs baseline: 1.0161x; 1.0161x over previous
#include <cuda_runtime.h>
#include <cstdint>

// Problem constants (fixed shapes)
#define PN    100000   // nodes
#define PE    100000   // hyperedges
#define PNNZ  800000   // edges (nnz)
#define PR    4        // ranks
#define PF    64       // features

#define NTILE 1024
#define NB_C  ((PE + NTILE - 1) / NTILE)   // 98
#define NB_R  ((PN + NTILE - 1) / NTILE)   // 98
#define OFF_R (NB_C + 1)                   // r-segment base in g_bsum (c sentinel at NB_C)

// ---- scratch (__device__ globals; no allocation). ~41 MB total.
// RULE (hard-won in rounds 3-6): these symbols are referenced ONLY from
// device code; never passed as host-side kernel arguments (host shadow
// address = UB = 128 MB checkpoint violation).
__device__ int    g_is64;
__device__ int    g_cnt_c[PE];           // counted UP by histogram, DOWN to 0 by scatter (self-clean)
__device__ int    g_cnt_r[PN];
__device__ int    g_ptr_c[PE];           // tile-local exclusive prefix
__device__ int    g_ptr_r[PN];
__device__ int    g_bsum[OFF_R + NB_R + 1];  // exclusive tile bases + sentinels
__device__ __align__(16) float4 g_scales[PE];                 // (rm0,rm1,rm2,_)[he_idxs[c]]  1.6 MB
__device__ __align__(16) float  g_he_feat[(size_t)PE * PF];   // 25.6 MB dense
__device__ __align__(8)  int2   g_e1[PNNZ];   // by col, index-ordered bins: (row, val bits)   6.4 MB
__device__ __align__(8)  int2   g_e2[PNNZ];   // by row, index-ordered bins: (col, val bits)   6.4 MB

__device__ __forceinline__ long long load_idx(const void* p, long long i, int is64) {
    if (is64) return ((const long long*)p)[i];
    return (long long)((const int*)p)[i];
}

// --- dtype sniff, warp-parallel (every replay).
// int64 LE indices < 2^31 -> every odd 32-bit word is 0. 1024 words checked.
__global__ void detect_dtype(const void* rows) {
    const int* p = (const int*)rows;
    int lane = threadIdx.x;
    int found = 0;
    #pragma unroll
    for (int k = 0; k < 32; k++) {
        int i = lane + 32 * k;
        if (p[2 * i + 1] != 0) found = 1;
    }
    unsigned any = __ballot_sync(0xFFFFFFFFu, found);
    if (lane == 0) g_is64 = (any == 0u);
}

// --- histogram edges by col and by row; fused per-hyperedge scale precompute.
//     Counters arrive zeroed: BSS init on first run, scatter's count-down after.
__global__ void histogram_edges(const void* __restrict__ rows,
                                const void* __restrict__ cols,
                                const void* __restrict__ he_idxs,
                                const float* __restrict__ rank_masks) {
    int is64 = g_is64;
    long long e = (long long)blockIdx.x * blockDim.x + threadIdx.x;
    if (e >= PNNZ) return;
    int row = (int)load_idx(rows, e, is64);
    int col = (int)load_idx(cols, e, is64);
    atomicAdd(&g_cnt_c[col], 1);
    atomicAdd(&g_cnt_r[row], 1);
    if (e < PE) {
        long long he = load_idx(he_idxs, e, is64);
        g_scales[e] = make_float4(rank_masks[he],
                                  rank_masks[(size_t)PE + he],
                                  rank_masks[(size_t)2 * PE + he],
                                  0.0f);
    }
}

// --- scan phase 1: per-tile local exclusive prefix -> ptr; tile total -> g_bsum slot.
__global__ void scan_tiles() {
    __shared__ int sm[NTILE];
    int b = blockIdx.x;
    bool isC = (b < NB_C);
    const int* cnt = isC ? g_cnt_c : g_cnt_r;
    int*       ptr = isC ? g_ptr_c : g_ptr_r;
    int n    = isC ? PE : PN;
    int tile = isC ? b : b - NB_C;
    int slot = isC ? b : OFF_R + tile;
    int t = threadIdx.x;
    int i = tile * NTILE + t;
    int v = (i < n) ? cnt[i] : 0;
    sm[t] = v;
    __syncthreads();
    #pragma unroll
    for (int d = 1; d < NTILE; d <<= 1) {
        int u = (t >= d) ? sm[t - d] : 0;
        __syncthreads();
        sm[t] += u;
        __syncthreads();
    }
    if (i < n) ptr[i] = sm[t] - v;             // tile-local exclusive
    if (t == NTILE - 1) g_bsum[slot] = sm[t];  // tile total (aggregate)
}

// --- scan phase 2: aggregates -> exclusive tile bases (in place) + sentinels.
__global__ void scan_bsums() {
    __shared__ int sm[256];
    int t = threadIdx.x;          // 0..255
    int seg = t >> 7;             // 0 = c, 1 = r
    int j = t & 127;
    int slot = (seg == 0) ? j : OFF_R + j;
    bool valid = (seg == 0) ? (j < NB_C) : (j < NB_R);
    int v = valid ? g_bsum[slot] : 0;
    sm[t] = v;
    __syncthreads();
    #pragma unroll
    for (int d = 1; d < 128; d <<= 1) {
        int u = (j >= d) ? sm[t - d] : 0;
        __syncthreads();
        sm[t] += u;
        __syncthreads();
    }
    if (valid) g_bsum[slot] = sm[t] - v;       // exclusive base
    if (t == 0) { g_bsum[NB_C] = PNNZ; g_bsum[OFF_R + NB_R] = PNNZ; }  // sentinels
}

// --- scatter edges into index-ordered bins. Slot = local prefix + tile base +
//     countdown of cnt (atomicSub). cnt ends at exactly 0 -> self-clean for
//     the next replay's histogram. No cur arrays, no offset-apply kernel.
__global__ void scatter_fill(const float* __restrict__ vals,
                             const void* __restrict__ rows,
                             const void* __restrict__ cols) {
    int is64 = g_is64;
    long long e = (long long)blockIdx.x * blockDim.x + threadIdx.x;
    if (e >= PNNZ) return;
    int row = (int)load_idx(rows, e, is64);
    int col = (int)load_idx(cols, e, is64);
    int vbits = __float_as_int(vals[e]);

    int rel1 = atomicSub(&g_cnt_c[col], 1) - 1;
    int p1 = g_ptr_c[col] + g_bsum[col >> 10] + rel1;
    g_e1[p1] = make_int2(row, vbits);

    int rel2 = atomicSub(&g_cnt_r[row], 1) - 1;
    int p2 = g_ptr_r[row] + g_bsum[OFF_R + (row >> 10)] + rel2;
    g_e2[p2] = make_int2(col, vbits);
}

// --- pass 1 (gather): he_feat[c, :] = sum over edges in col-bin c of x[row]*val
//     16 threads per hyperedge; each owns one float4 of the 64-float row.
__global__ void gather_edge_feat(const float4* __restrict__ x4) {
    long long g = ((long long)blockIdx.x * blockDim.x + threadIdx.x) >> 4;
    int sub = threadIdx.x & 15;
    if (g >= PE) return;
    int tile = (int)(g >> 10);
    int j    = (int)(g & 1023);
    int base = g_bsum[tile];
    int beg = g_ptr_c[g] + base;
    int end = (j == 1023 || g == PE - 1) ? g_bsum[tile + 1]
                                         : g_ptr_c[g + 1] + base;
    float4 acc = make_float4(0.f, 0.f, 0.f, 0.f);
    #pragma unroll 2
    for (int i = beg; i < end; i++) {
        int2 eRec = g_e1[i];
        float v = __int_as_float(eRec.y);
        float4 a = x4[(long long)eRec.x * 16 + sub];
        acc.x += a.x * v; acc.y += a.y * v; acc.z += a.z * v; acc.w += a.w * v;
    }
    ((float4*)g_he_feat)[g * 16 + sub] = acc;   // dense, coalesced
}

// --- pass 2 (gather, fused with rank-3 init):
//     out[n, r, :] = sum over edges in row-bin n of
//         (g_scales[col].r * val) * he_feat[col, :]   (r = 0..2)
//     out[n, 3, :] = x[n, :]   -- full 1 KB node row written contiguously.
__global__ void gather_node_feat(float4* __restrict__ out4,
                                 const float4* __restrict__ x4) {
    long long n = ((long long)blockIdx.x * blockDim.x + threadIdx.x) >> 4;
    int sub = threadIdx.x & 15;
    if (n >= PN) return;
    int tile = (int)(n >> 10);
    int j    = (int)(n & 1023);
    int base = g_bsum[OFF_R + tile];
    int beg = g_ptr_r[n] + base;
    int end = (j == 1023 || n == PN - 1) ? g_bsum[OFF_R + tile + 1]
                                         : g_ptr_r[n + 1] + base;
    const float4* hf4 = (const float4*)g_he_feat;
    float4 a0 = make_float4(0.f, 0.f, 0.f, 0.f);
    float4 a1 = a0, a2 = a0;
    #pragma unroll 2
    for (int i = beg; i < end; i++) {
        int2 m = g_e2[i];
        int col = m.x;
        float v = __int_as_float(m.y);
        float4 sc = g_scales[col];          // broadcast across the 16 lanes; L2-hot
        float4 h  = hf4[(long long)col * 16 + sub];
        float s0 = sc.x * v, s1 = sc.y * v, s2 = sc.z * v;
        a0.x += h.x * s0; a0.y += h.y * s0; a0.z += h.z * s0; a0.w += h.w * s0;
        a1.x += h.x * s1; a1.y += h.y * s1; a1.z += h.z * s1; a1.w += h.w * s1;
        a2.x += h.x * s2; a2.y += h.y * s2; a2.z += h.z * s2; a2.w += h.w * s2;
    }
    float4* o = out4 + n * 64;          // 64 float4 per node row (R*F = 256 floats)
    o[sub]      = a0;
    o[16 + sub] = a1;
    o[32 + sub] = a2;
    o[48 + sub] = x4[n * 16 + sub];     // fused rank-3 = x
}

extern "C" void kernel_launch(void* const* d_in, const int* in_sizes, int n_in,
                              void* d_out, int out_size) {
    const float* x          = (const float*)d_in[0];   // (N, F)
    const float* rank_masks = (const float*)d_in[1];   // (R, E)
    const float* vals       = (const float*)d_in[2];   // (NNZ,)
    const void*  he_idxs    = d_in[3];                 // (E,)
    const void*  rows       = d_in[4];                 // (NNZ,)
    const void*  cols       = d_in[5];                 // (NNZ,)
    float4* out4 = (float4*)d_out;                     // (N, R, F)

    detect_dtype<<<1, 32>>>(rows);

    histogram_edges<<<(PNNZ + 255) / 256, 256>>>(rows, cols, he_idxs, rank_masks);

    scan_tiles<<<NB_C + NB_R, NTILE>>>();
    scan_bsums<<<1, 256>>>();

    scatter_fill<<<(PNNZ + 255) / 256, 256>>>(vals, rows, cols);

    {
        long long threads = (long long)PE * 16;
        gather_edge_feat<<<(int)((threads + 255) / 256), 256>>>((const float4*)x);
    }
    {
        long long threads = (long long)PN * 16;
        gather_node_feat<<<(int)((threads + 255) / 256), 256>>>(out4, (const float4*)x);
    }
}

// round 14
// speedup vs baseline: 1.0926x; 1.0752x over previous
#include <cuda_runtime.h>
#include <cstdint>

// Problem constants (fixed shapes)
#define PN    100000   // nodes
#define PE    100000   // hyperedges
#define PNNZ  800000   // edges (nnz)
#define PR    4        // ranks
#define PF    64       // features

#define NTILE 1024
#define NB_C  ((PE + NTILE - 1) / NTILE)   // 98
#define NB_R  ((PN + NTILE - 1) / NTILE)   // 98
#define OFF_R (NB_C + 1)                   // r-segment base in g_bsum (c sentinel at NB_C)

// ---- scratch (__device__ globals; no allocation). ~41 MB total.
// RULE (hard-won in rounds 3-6): these symbols are referenced ONLY from
// device code; never passed as host-side kernel arguments (host shadow
// address = UB = 128 MB checkpoint violation).
__device__ int    g_is64;
__device__ int    g_not1;                // 1 if any vals[e] != 1.0f (slow path)
__device__ int    g_cnt_c[PE];           // counted UP by histogram, DOWN to 0 by scatter (self-clean)
__device__ int    g_cnt_r[PN];
__device__ int    g_ptr_c[PE];           // tile-local exclusive prefix
__device__ int    g_ptr_r[PN];
__device__ int    g_bsum[OFF_R + NB_R + 1];  // exclusive tile bases + sentinels
__device__ __align__(16) float4 g_scales[PE];                 // (rm0,rm1,rm2,_)[he_idxs[c]]  1.6 MB
__device__ __align__(16) float  g_he_feat[(size_t)PE * PF];   // 25.6 MB dense
__device__ __align__(8)  int2   g_e1[PNNZ];   // by col bins: (row[,val]) — 4B records on fast path
__device__ __align__(8)  int2   g_e2[PNNZ];   // by row bins: (col[,val]) — 4B records on fast path

__device__ __forceinline__ long long load_idx(const void* p, long long i, int is64) {
    if (is64) return ((const long long*)p)[i];
    return (long long)((const int*)p)[i];
}

// --- dtype sniff, warp-parallel + per-replay flag reset.
// int64 LE indices < 2^31 -> every odd 32-bit word is 0. 1024 words checked.
__global__ void detect_dtype(const void* rows) {
    const int* p = (const int*)rows;
    int lane = threadIdx.x;
    int found = 0;
    #pragma unroll
    for (int k = 0; k < 32; k++) {
        int i = lane + 32 * k;
        if (p[2 * i + 1] != 0) found = 1;
    }
    unsigned any = __ballot_sync(0xFFFFFFFFu, found);
    if (lane == 0) {
        g_is64 = (any == 0u);
        g_not1 = 0;
    }
}

// --- histogram edges by col and by row; fused per-hyperedge scale precompute
//     AND vals==1.0 screening (sets g_not1 if any val deviates).
//     Counters arrive zeroed: BSS init on first run, scatter's count-down after.
__global__ void histogram_edges(const void* __restrict__ rows,
                                const void* __restrict__ cols,
                                const void* __restrict__ he_idxs,
                                const float* __restrict__ rank_masks,
                                const float* __restrict__ vals) {
    int is64 = g_is64;
    long long e = (long long)blockIdx.x * blockDim.x + threadIdx.x;
    if (e >= PNNZ) return;
    int row = (int)load_idx(rows, e, is64);
    int col = (int)load_idx(cols, e, is64);
    atomicAdd(&g_cnt_c[col], 1);
    atomicAdd(&g_cnt_r[row], 1);
    if (vals[e] != 1.0f) atomicOr(&g_not1, 1);
    if (e < PE) {
        long long he = load_idx(he_idxs, e, is64);
        g_scales[e] = make_float4(rank_masks[he],
                                  rank_masks[(size_t)PE + he],
                                  rank_masks[(size_t)2 * PE + he],
                                  0.0f);
    }
}

// --- scan phase 1: per-tile local exclusive prefix -> ptr; tile total -> g_bsum slot.
__global__ void scan_tiles() {
    __shared__ int sm[NTILE];
    int b = blockIdx.x;
    bool isC = (b < NB_C);
    const int* cnt = isC ? g_cnt_c : g_cnt_r;
    int*       ptr = isC ? g_ptr_c : g_ptr_r;
    int n    = isC ? PE : PN;
    int tile = isC ? b : b - NB_C;
    int slot = isC ? b : OFF_R + tile;
    int t = threadIdx.x;
    int i = tile * NTILE + t;
    int v = (i < n) ? cnt[i] : 0;
    sm[t] = v;
    __syncthreads();
    #pragma unroll
    for (int d = 1; d < NTILE; d <<= 1) {
        int u = (t >= d) ? sm[t - d] : 0;
        __syncthreads();
        sm[t] += u;
        __syncthreads();
    }
    if (i < n) ptr[i] = sm[t] - v;             // tile-local exclusive
    if (t == NTILE - 1) g_bsum[slot] = sm[t];  // tile total (aggregate)
}

// --- scan phase 2: aggregates -> exclusive tile bases (in place) + sentinels.
__global__ void scan_bsums() {
    __shared__ int sm[256];
    int t = threadIdx.x;          // 0..255
    int seg = t >> 7;             // 0 = c, 1 = r
    int j = t & 127;
    int slot = (seg == 0) ? j : OFF_R + j;
    bool valid = (seg == 0) ? (j < NB_C) : (j < NB_R);
    int v = valid ? g_bsum[slot] : 0;
    sm[t] = v;
    __syncthreads();
    #pragma unroll
    for (int d = 1; d < 128; d <<= 1) {
        int u = (j >= d) ? sm[t - d] : 0;
        __syncthreads();
        sm[t] += u;
        __syncthreads();
    }
    if (valid) g_bsum[slot] = sm[t] - v;       // exclusive base
    if (t == 0) { g_bsum[NB_C] = PNNZ; g_bsum[OFF_R + NB_R] = PNNZ; }  // sentinels
}

// --- scatter edges into index-ordered bins. Slot = local prefix + tile base +
//     countdown of cnt (atomicSub); cnt ends at exactly 0 -> self-clean.
//     Fast path (vals all 1.0): 4-byte records, no vals read.
__global__ void scatter_fill(const float* __restrict__ vals,
                             const void* __restrict__ rows,
                             const void* __restrict__ cols) {
    int is64 = g_is64;
    int not1 = g_not1;            // uniform across grid
    long long e = (long long)blockIdx.x * blockDim.x + threadIdx.x;
    if (e >= PNNZ) return;
    int row = (int)load_idx(rows, e, is64);
    int col = (int)load_idx(cols, e, is64);

    int rel1 = atomicSub(&g_cnt_c[col], 1) - 1;
    int p1 = g_ptr_c[col] + g_bsum[col >> 10] + rel1;
    int rel2 = atomicSub(&g_cnt_r[row], 1) - 1;
    int p2 = g_ptr_r[row] + g_bsum[OFF_R + (row >> 10)] + rel2;

    if (not1) {
        int vbits = __float_as_int(vals[e]);
        g_e1[p1] = make_int2(row, vbits);
        g_e2[p2] = make_int2(col, vbits);
    } else {
        ((int*)g_e1)[p1] = row;
        ((int*)g_e2)[p2] = col;
    }
}

// --- pass 1 (gather): he_feat[c, :] = sum over edges in col-bin c of x[row]*val
//     16 threads per hyperedge; each owns one float4 of the 64-float row.
__global__ void gather_edge_feat(const float4* __restrict__ x4) {
    long long g = ((long long)blockIdx.x * blockDim.x + threadIdx.x) >> 4;
    int sub = threadIdx.x & 15;
    if (g >= PE) return;
    int tile = (int)(g >> 10);
    int j    = (int)(g & 1023);
    int base = g_bsum[tile];
    int beg = g_ptr_c[g] + base;
    int end = (j == 1023 || g == PE - 1) ? g_bsum[tile + 1]
                                         : g_ptr_c[g + 1] + base;
    float4 acc = make_float4(0.f, 0.f, 0.f, 0.f);
    if (g_not1) {
        #pragma unroll 2
        for (int i = beg; i < end; i++) {
            int2 eRec = g_e1[i];
            float v = __int_as_float(eRec.y);
            float4 a = x4[(long long)eRec.x * 16 + sub];
            acc.x += a.x * v; acc.y += a.y * v; acc.z += a.z * v; acc.w += a.w * v;
        }
    } else {
        const int* e1i = (const int*)g_e1;
        #pragma unroll 2
        for (int i = beg; i < end; i++) {
            int r = e1i[i];
            float4 a = x4[(long long)r * 16 + sub];
            acc.x += a.x; acc.y += a.y; acc.z += a.z; acc.w += a.w;
        }
    }
    ((float4*)g_he_feat)[g * 16 + sub] = acc;   // dense, coalesced
}

// --- pass 2 (gather, fused with rank-3 init):
//     out[n, r, :] = sum over edges in row-bin n of
//         (g_scales[col].r * val) * he_feat[col, :]   (r = 0..2)
//     out[n, 3, :] = x[n, :]   -- full 1 KB node row written contiguously.
__global__ void gather_node_feat(float4* __restrict__ out4,
                                 const float4* __restrict__ x4) {
    long long n = ((long long)blockIdx.x * blockDim.x + threadIdx.x) >> 4;
    int sub = threadIdx.x & 15;
    if (n >= PN) return;
    int tile = (int)(n >> 10);
    int j    = (int)(n & 1023);
    int base = g_bsum[OFF_R + tile];
    int beg = g_ptr_r[n] + base;
    int end = (j == 1023 || n == PN - 1) ? g_bsum[OFF_R + tile + 1]
                                         : g_ptr_r[n + 1] + base;
    const float4* hf4 = (const float4*)g_he_feat;
    float4 a0 = make_float4(0.f, 0.f, 0.f, 0.f);
    float4 a1 = a0, a2 = a0;
    if (g_not1) {
        #pragma unroll 2
        for (int i = beg; i < end; i++) {
            int2 m = g_e2[i];
            int col = m.x;
            float v = __int_as_float(m.y);
            float4 sc = g_scales[col];
            float4 h  = hf4[(long long)col * 16 + sub];
            float s0 = sc.x * v, s1 = sc.y * v, s2 = sc.z * v;
            a0.x += h.x * s0; a0.y += h.y * s0; a0.z += h.z * s0; a0.w += h.w * s0;
            a1.x += h.x * s1; a1.y += h.y * s1; a1.z += h.z * s1; a1.w += h.w * s1;
            a2.x += h.x * s2; a2.y += h.y * s2; a2.z += h.z * s2; a2.w += h.w * s2;
        }
    } else {
        const int* e2i = (const int*)g_e2;
        #pragma unroll 2
        for (int i = beg; i < end; i++) {
            int col = e2i[i];
            float4 sc = g_scales[col];          // broadcast across 16 lanes; L2-hot
            float4 h  = hf4[(long long)col * 16 + sub];
            a0.x += h.x * sc.x; a0.y += h.y * sc.x; a0.z += h.z * sc.x; a0.w += h.w * sc.x;
            a1.x += h.x * sc.y; a1.y += h.y * sc.y; a1.z += h.z * sc.y; a1.w += h.w * sc.y;
            a2.x += h.x * sc.z; a2.y += h.y * sc.z; a2.z += h.z * sc.z; a2.w += h.w * sc.z;
        }
    }
    float4* o = out4 + n * 64;          // 64 float4 per node row (R*F = 256 floats)
    o[sub]      = a0;
    o[16 + sub] = a1;
    o[32 + sub] = a2;
    o[48 + sub] = x4[n * 16 + sub];     // fused rank-3 = x
}

extern "C" void kernel_launch(void* const* d_in, const int* in_sizes, int n_in,
                              void* d_out, int out_size) {
    const float* x          = (const float*)d_in[0];   // (N, F)
    const float* rank_masks = (const float*)d_in[1];   // (R, E)
    const float* vals       = (const float*)d_in[2];   // (NNZ,)
    const void*  he_idxs    = d_in[3];                 // (E,)
    const void*  rows       = d_in[4];                 // (NNZ,)
    const void*  cols       = d_in[5];                 // (NNZ,)
    float4* out4 = (float4*)d_out;                     // (N, R, F)

    detect_dtype<<<1, 32>>>(rows);

    histogram_edges<<<(PNNZ + 255) / 256, 256>>>(rows, cols, he_idxs, rank_masks, vals);

    scan_tiles<<<NB_C + NB_R, NTILE>>>();
    scan_bsums<<<1, 256>>>();

    scatter_fill<<<(PNNZ + 255) / 256, 256>>>(vals, rows, cols);

    {
        long long threads = (long long)PE * 16;
        gather_edge_feat<<<(int)((threads + 255) / 256), 256>>>((const float4*)x);
    }
    {
        long long threads = (long long)PN * 16;
        gather_node_feat<<<(int)((threads + 255) / 256), 256>>>(out4, (const float4*)x);
    }
}